// round 5
// baseline (speedup 1.0000x reference)
#include <cuda_runtime.h>
#include <cstddef>
#include <cstdint>

#define NEGV -1000000000.0f
#define HDIM 128
#define NMAX 12288
// mask: 1 bit per output element
#define NMASK_WORDS ((NMAX * (size_t)NMAX) / 32)   // 4,718,592

__device__ float2  g_p[NMAX];
__device__ uint32_t g_mask[NMASK_WORDS];           // 18.9 MB

// K1: blocks [0, nZeroBlks) zero the mask; blocks [nZeroBlks, +384) do partials.
__global__ void __launch_bounds__(256)
prep_kernel(const float* __restrict__ h,
            const float* __restrict__ W,
            int N, int nZeroBlks) {
    const int tid = threadIdx.x;
    if ((int)blockIdx.x < nZeroBlks) {
        // zero mask: 2 uint4 (8 words) per thread
        uint4* m4 = reinterpret_cast<uint4*>(g_mask);
        const uint4 z = make_uint4(0u, 0u, 0u, 0u);
        size_t base = (size_t)blockIdx.x * 512 + tid;
        m4[base] = z;
        m4[base + 256] = z;
    } else {
        // partials: 8 lanes per node, 4 nodes/warp, 32 nodes/block
        const int pbid = blockIdx.x - nZeroBlks;
        const int warp = tid >> 5;
        const int lane = tid & 31;
        const int sub  = lane & 7;
        const int grp  = lane >> 3;
        const int node = pbid * 32 + warp * 4 + grp;
        if (node < N) {
            const float* hp = h + (size_t)node * HDIM + sub * 16;
            const float* wp = W + sub * 16;
            float ad = 0.0f, as = 0.0f;
            #pragma unroll
            for (int k = 0; k < 4; k++) {
                const float4 hv = *reinterpret_cast<const float4*>(hp + k * 4);
                const float4 wd = *reinterpret_cast<const float4*>(wp + k * 4);
                const float4 ws = *reinterpret_cast<const float4*>(wp + HDIM + k * 4);
                ad += hv.x * wd.x + hv.y * wd.y + hv.z * wd.z + hv.w * wd.w;
                as += hv.x * ws.x + hv.y * ws.y + hv.z * ws.z + hv.w * ws.w;
            }
            #pragma unroll
            for (int o = 4; o; o >>= 1) {
                ad += __shfl_xor_sync(0xffffffffu, ad, o);
                as += __shfl_xor_sync(0xffffffffu, as, o);
            }
            if (sub == 0) g_p[node] = make_float2(ad, as);
        }
    }
}

// K2: per edge — write score into out, set its mask bit.
__global__ void __launch_bounds__(256)
scatter_kernel(const int* __restrict__ sources,
               const int* __restrict__ dests,
               const float* __restrict__ weights,
               const float* __restrict__ W,
               const float* __restrict__ b,
               float* __restrict__ out, int E, int N) {
    int e = blockIdx.x * blockDim.x + threadIdx.x;
    if (e >= E) return;
    const int s = sources[e];
    const int d = dests[e];
    const float val = g_p[d].x + g_p[s].y + weights[e] * W[2 * HDIM] + b[0];
    const size_t idx = (size_t)d * N + s;
    out[idx] = val;
    atomicOr(&g_mask[idx >> 5], 1u << ((unsigned)idx & 31u));
}

// K3: fill all elements whose mask bit is clear with NEG.
// Each thread: 4 float4s (stride-256 within block), nibble of mask per float4.
__global__ void __launch_bounds__(256)
fill_kernel(float4* __restrict__ out, int n4) {
    const int tid = threadIdx.x;
    const int g0 = blockIdx.x * 1024 + tid;
    const float4 v = make_float4(NEGV, NEGV, NEGV, NEGV);

    uint32_t m[4];
    #pragma unroll
    for (int k = 0; k < 4; k++) {
        int g = g0 + k * 256;
        m[k] = (g < n4) ? g_mask[g >> 3] : 0xFFFFFFFFu;
    }
    #pragma unroll
    for (int k = 0; k < 4; k++) {
        int g = g0 + k * 256;
        if (g >= n4) continue;
        uint32_t nib = (m[k] >> ((g & 7) * 4)) & 0xFu;
        if (nib == 0u) {
            out[g] = v;
        } else {
            float* o = reinterpret_cast<float*>(out + g);
            if (!(nib & 1u)) o[0] = NEGV;
            if (!(nib & 2u)) o[1] = NEGV;
            if (!(nib & 4u)) o[2] = NEGV;
            if (!(nib & 8u)) o[3] = NEGV;
        }
    }
}

extern "C" void kernel_launch(void* const* d_in, const int* in_sizes, int n_in,
                              void* d_out, int out_size) {
    const float* h       = (const float*)d_in[0];
    const int*   sources = (const int*)d_in[1];
    const int*   dests   = (const int*)d_in[2];
    const float* weights = (const float*)d_in[3];
    const float* W       = (const float*)d_in[4];
    const float* b       = (const float*)d_in[5];
    float* out = (float*)d_out;

    const int N = in_sizes[0] / HDIM;     // 12288
    const int E = in_sizes[1];            // 393216

    long long total = (long long)N * N;
    int n4 = (int)(total >> 2);           // 37,748,736

    // K1: zero mask + partials
    const int nZeroBlks = (int)(NMASK_WORDS / (512 * 4) * 4) / 1;  // words / (8 per thread * 256 threads)
    const int zeroBlks  = (int)((NMASK_WORDS + 8 * 256 - 1) / (8 * 256));  // 2304
    const int partBlks  = (N + 31) / 32;                                   // 384
    prep_kernel<<<zeroBlks + partBlks, 256>>>(h, W, N, zeroBlks);
    (void)nZeroBlks;

    // K2: scatter edge scores + mask bits
    scatter_kernel<<<(E + 255) / 256, 256>>>(sources, dests, weights, W, b, out, E, N);

    // K3: masked fill
    fill_kernel<<<(n4 + 1023) / 1024, 256>>>((float4*)out, n4);
}

// round 6
// speedup vs baseline: 1.2645x; 1.2645x over previous
#include <cuda_runtime.h>
#include <cstddef>

#define NEGV -1000000000.0f
#define HDIM 128
#define NMAX 12288

// per-node partials: g_p[n].x = h[n].W[0:128), g_p[n].y = h[n].W[128:256)
__device__ float2 g_p[NMAX];

// Fused: blocks [0, nPartBlks) compute node partials; the rest fill `out`.
// The two roles touch disjoint memory -> no intra-kernel ordering needed.
__global__ void __launch_bounds__(256)
prep_fill_kernel(const float* __restrict__ h,
                 const float* __restrict__ W,
                 float4* __restrict__ out,
                 int N, int n4, int nPartBlks) {
    const int tid = threadIdx.x;
    const int bid = blockIdx.x;

    if (bid < nPartBlks) {
        // partials: 8 lanes per node, 4 nodes/warp, 32 nodes/block
        const int warp = tid >> 5;
        const int lane = tid & 31;
        const int sub  = lane & 7;
        const int grp  = lane >> 3;
        const int node = bid * 32 + warp * 4 + grp;
        if (node < N) {
            const float* hp = h + (size_t)node * HDIM + sub * 16;
            const float* wp = W + sub * 16;
            float ad = 0.0f, as = 0.0f;
            #pragma unroll
            for (int k = 0; k < 4; k++) {
                const float4 hv = *reinterpret_cast<const float4*>(hp + k * 4);
                const float4 wd = *reinterpret_cast<const float4*>(wp + k * 4);
                const float4 ws = *reinterpret_cast<const float4*>(wp + HDIM + k * 4);
                ad += hv.x * wd.x + hv.y * wd.y + hv.z * wd.z + hv.w * wd.w;
                as += hv.x * ws.x + hv.y * ws.y + hv.z * ws.z + hv.w * ws.w;
            }
            #pragma unroll
            for (int o = 4; o; o >>= 1) {
                ad += __shfl_xor_sync(0xffffffffu, ad, o);
                as += __shfl_xor_sync(0xffffffffu, as, o);
            }
            if (sub == 0) g_p[node] = make_float2(ad, as);
        }
    } else {
        // fill: 4 float4 stores per thread, plain stores (fastest measured path)
        const int fbid = bid - nPartBlks;
        const float4 v = make_float4(NEGV, NEGV, NEGV, NEGV);
        const int base = fbid * 1024 + tid;
        #pragma unroll
        for (int k = 0; k < 4; k++) {
            int idx = base + k * 256;
            if (idx < n4) out[idx] = v;
        }
    }
}

// Scatter: 2 edges per thread for load ILP; g_p gathers hit L2.
__global__ void __launch_bounds__(256)
scatter_kernel(const int* __restrict__ sources,
               const int* __restrict__ dests,
               const float* __restrict__ weights,
               const float* __restrict__ W,
               const float* __restrict__ b,
               float* __restrict__ out, int E, int N) {
    const int t = blockIdx.x * blockDim.x + threadIdx.x;
    const float wW = __ldg(W + 2 * HDIM);
    const float bb = __ldg(b);

    const int e0 = t * 2;
    if (e0 + 1 < E) {
        int s0 = sources[e0],     d0 = dests[e0];
        int s1 = sources[e0 + 1], d1 = dests[e0 + 1];
        float w0 = weights[e0], w1 = weights[e0 + 1];
        float2 pd0 = __ldg(&g_p[d0]);
        float2 ps0 = __ldg(&g_p[s0]);
        float2 pd1 = __ldg(&g_p[d1]);
        float2 ps1 = __ldg(&g_p[s1]);
        out[(size_t)d0 * N + s0] = pd0.x + ps0.y + w0 * wW + bb;
        out[(size_t)d1 * N + s1] = pd1.x + ps1.y + w1 * wW + bb;
    } else if (e0 < E) {
        int s = sources[e0], d = dests[e0];
        float2 pd = __ldg(&g_p[d]);
        float2 ps = __ldg(&g_p[s]);
        out[(size_t)d * N + s] = pd.x + ps.y + weights[e0] * wW + bb;
    }
}

extern "C" void kernel_launch(void* const* d_in, const int* in_sizes, int n_in,
                              void* d_out, int out_size) {
    const float* h       = (const float*)d_in[0];
    const int*   sources = (const int*)d_in[1];
    const int*   dests   = (const int*)d_in[2];
    const float* weights = (const float*)d_in[3];
    const float* W       = (const float*)d_in[4];
    const float* b       = (const float*)d_in[5];
    float* out = (float*)d_out;

    const int N = in_sizes[0] / HDIM;     // 12288
    const int E = in_sizes[1];            // 393216

    long long total = (long long)N * N;
    int n4 = (int)(total >> 2);           // 37,748,736

    const int nPartBlks = (N + 31) / 32;            // 384
    const int nFillBlks = (n4 + 1023) / 1024;       // 36,864

    prep_fill_kernel<<<nPartBlks + nFillBlks, 256>>>(h, W, (float4*)out,
                                                     N, n4, nPartBlks);

    const int nEdgeThreads = (E + 1) / 2;           // 2 edges/thread
    scatter_kernel<<<(nEdgeThreads + 255) / 256, 256>>>(sources, dests, weights,
                                                        W, b, out, E, N);
}